// round 12
// baseline (speedup 1.0000x reference)
#include <cuda_runtime.h>
#include <cuda_bf16.h>

// Problem constants: B=2, H=1, LQ=LK=512, D=64, HID=128
#define NB   2
#define L    512
#define DD   64
#define HID  128

// Scratch (allocation-free rule: __device__ globals)
__device__ float  g_vp[NB * L * DD];             // projected V
__device__ float  g_qaqb[NB * L * HID * 2];      // interleaved (qa, qb) per (row, h)
__device__ float2 g_kbkaT[NB * HID * L];         // TRANSPOSED: [b][h][j] -> (kb+b1, ka+b1)
__device__ float  g_Cq[NB * L];                  // Σ_h (qa+qb)·w2/2 per q-row
__device__ float  g_Ck[NB * L];                  // Σ_h (kb'+ka')·w2/2 per k-row

// ---------------------------------------------------------------------------
// Kernel A: projections + pairwise-MLP feature precompute + rank-1 terms.
// grid = NB * (L/4) = 256 blocks, 256 threads.
// ---------------------------------------------------------------------------
__global__ __launch_bounds__(256) void prep_kernel(
    const float* __restrict__ q, const float* __restrict__ k,
    const float* __restrict__ v, const float* __restrict__ Ww,
    const float* __restrict__ wb, const float* __restrict__ W1,
    const float* __restrict__ b1, const float* __restrict__ W2)
{
    __shared__ float q_s[4][DD], k_s[4][DD], v_s[4][DD];
    __shared__ float qp_s[4][DD], kp_s[4][DD];
    __shared__ float red_c[8][4];        // per-warp partial rank-1 sums

    const int tid  = threadIdx.x;
    const int b    = blockIdx.x >> 7;
    const int r0   = (blockIdx.x & 127) * 4;
    const int base = (b * L + r0) * DD;

    {
        int r = tid >> 6, e = tid & 63;
        q_s[r][e] = q[base + tid];
        k_s[r][e] = k[base + tid];
        v_s[r][e] = v[base + tid];
    }
    __syncthreads();

    {
        int pj = tid >> 6, d = tid & 63;
        if (pj < 3) {
            const float (*src)[DD] = (pj == 0) ? q_s : (pj == 1) ? k_s : v_s;
            float acc[4];
            float bias = wb[d];
            #pragma unroll
            for (int r = 0; r < 4; r++) acc[r] = bias;
            #pragma unroll 8
            for (int e = 0; e < DD; e++) {
                float w = Ww[e * DD + d];
                #pragma unroll
                for (int r = 0; r < 4; r++) acc[r] += src[r][e] * w;
            }
            #pragma unroll
            for (int r = 0; r < 4; r++) {
                if (pj == 0)      qp_s[r][d] = acc[r];
                else if (pj == 1) kp_s[r][d] = acc[r];
                else              g_vp[base + r * DD + d] = acc[r];
            }
        }
    }
    __syncthreads();

    {
        int half = tid >> 7;     // 0: q-features, 1: k-features
        int h    = tid & 127;
        const float (*src)[DD] = half ? kp_s : qp_s;
        float accA[4] = {0.f, 0.f, 0.f, 0.f};   // · W1q
        float accB[4] = {0.f, 0.f, 0.f, 0.f};   // · W1k
        #pragma unroll 8
        for (int e = 0; e < DD; e++) {
            float w1q = W1[e * HID + h];
            float w1k = W1[(DD + e) * HID + h];
            #pragma unroll
            for (int r = 0; r < 4; r++) {
                float x = src[r][e];
                accA[r] += x * w1q;
                accB[r] += x * w1k;
            }
        }
        float bb = b1[h];
        float w2h = 0.5f * W2[h];
        float c[4];
        #pragma unroll
        for (int r = 0; r < 4; r++) {
            if (!half) {
                int off = ((b * L + r0 + r) * HID + h) * 2;
                g_qaqb[off + 0] = accA[r];                 // qa
                g_qaqb[off + 1] = accB[r];                 // qb
                c[r] = (accA[r] + accB[r]) * w2h;          // (qa+qb)·w2/2
            } else {
                float kb = accB[r] + bb, ka = accA[r] + bb;
                g_kbkaT[(b * HID + h) * L + (r0 + r)] = make_float2(kb, ka);
                c[r] = (kb + ka) * w2h;                    // (kb'+ka')·w2/2
            }
        }
        // block-reduce c over the 128 h of each half (4 warps per half)
        #pragma unroll
        for (int r = 0; r < 4; r++) {
            #pragma unroll
            for (int o = 16; o > 0; o >>= 1)
                c[r] += __shfl_xor_sync(0xffffffffu, c[r], o);
        }
        int warp = tid >> 5;
        if ((tid & 31) == 0) {
            #pragma unroll
            for (int r = 0; r < 4; r++) red_c[warp][r] = c[r];
        }
    }
    __syncthreads();

    if (tid < 8) {
        int half = tid >> 2, r = tid & 3;
        int w0 = half * 4;
        float s = red_c[w0][r] + red_c[w0 + 1][r] + red_c[w0 + 2][r] + red_c[w0 + 3][r];
        if (half == 0) g_Cq[b * L + r0 + r] = s;
        else           g_Ck[b * L + r0 + r] = s;
    }
}

// ---------------------------------------------------------------------------
// Kernel B: grid = NB*(L/2) = 512 blocks, 512 threads = 16 warps, 3 blocks/SM.
// Block covers 2 i-rows. Warp (jh, jq): jh = h-half (64 h), jq = j-slice of 64.
// Score loop: relu(x) = (x+|x|)/2 — rank-1 parts precomputed in prep, pairwise
// part is FADD + FFMA(|t|, w2/2) only.
// ---------------------------------------------------------------------------
__global__ __launch_bounds__(512, 3) void attn_kernel(
    const float* __restrict__ mask, const float* __restrict__ Wd,
    const float* __restrict__ db,   const float* __restrict__ W2,
    const float* __restrict__ b2,   float* __restrict__ out)
{
    __shared__ float4 qq_s[HID];         // (qa0,qb0,qa1,qb1) per h
    __shared__ float  w2_s[HID];         // w2/2
    __shared__ float  attn_s[2][L];
    __shared__ float  sp[8][32][4];      // jh=1 partial scores [jq][lane][4]
    __shared__ float  red_m[2][8], red_s[2][8];
    __shared__ float  o_part[2][16][DD];

    const int tid   = threadIdx.x;
    const int warp  = tid >> 5;
    const int lane  = tid & 31;
    const int jq    = warp & 7;          // j-slice
    const int jh    = warp >> 3;         // h-half
    const int b     = blockIdx.x >> 8;   // / 256
    const int itile = blockIdx.x & 255;
    const int row0  = b * L + itile * 2;

    // Stage packed q-features + W2/2
    if (tid < HID) {
        const float2* q0 = (const float2*)(g_qaqb + (size_t)row0 * (HID * 2));
        float2 a0 = q0[tid];
        float2 a1 = q0[HID + tid];
        qq_s[tid] = make_float4(a0.x, a0.y, a1.x, a1.y);
    } else if (tid < 2 * HID) {
        w2_s[tid - HID] = 0.5f * W2[tid - HID];
    }
    __syncthreads();

    // ---- |.|-part of scores over own h-half
    const float4* kt = reinterpret_cast<const float4*>(
        g_kbkaT + (size_t)(b * HID + jh * 64) * L) + jq * 32 + lane;

    float a00 = 0.f, a01 = 0.f, a10 = 0.f, a11 = 0.f;  // [row][j]

    #pragma unroll 4
    for (int hh = 0; hh < 64; hh++) {
        float4 kk = __ldg(kt + hh * (L / 2));   // (kb_j0, ka_j0, kb_j1, ka_j1)
        float4 qv = qq_s[jh * 64 + hh];         // (qa0, qb0, qa1, qb1)
        float  wh = w2_s[jh * 64 + hh];
        a00 = fmaf(fabsf(qv.x + kk.x), wh, a00);
        a00 = fmaf(fabsf(qv.y + kk.y), wh, a00);
        a01 = fmaf(fabsf(qv.x + kk.z), wh, a01);
        a01 = fmaf(fabsf(qv.y + kk.w), wh, a01);
        a10 = fmaf(fabsf(qv.z + kk.x), wh, a10);
        a10 = fmaf(fabsf(qv.w + kk.y), wh, a10);
        a11 = fmaf(fabsf(qv.z + kk.z), wh, a11);
        a11 = fmaf(fabsf(qv.w + kk.w), wh, a11);
    }

    // combine h-halves: jh=1 dumps partials, jh=0 accumulates
    if (jh == 1) {
        sp[jq][lane][0] = a00;
        sp[jq][lane][1] = a01;
        sp[jq][lane][2] = a10;
        sp[jq][lane][3] = a11;
    }
    __syncthreads();

    float s00, s01, s10, s11;
    if (jh == 0) {
        const float b2v2 = 2.f * b2[0];
        const float cq0 = g_Cq[row0], cq1 = g_Cq[row0 + 1];
        int jp = jq * 32 + lane;
        float2 ckv = ((const float2*)(g_Ck + (size_t)b * L))[jp];   // (Ck_j0, Ck_j1)
        const float2* mrow = (const float2*)(mask + (size_t)row0 * L) + jp;
        float2 mm0 = __ldg(mrow);
        float2 mm1 = __ldg(mrow + L / 2);
        s00 = a00 + sp[jq][lane][0] + cq0 + ckv.x + b2v2 + mm0.x * (-1e9f);
        s01 = a01 + sp[jq][lane][1] + cq0 + ckv.y + b2v2 + mm0.y * (-1e9f);
        s10 = a10 + sp[jq][lane][2] + cq1 + ckv.x + b2v2 + mm1.x * (-1e9f);
        s11 = a11 + sp[jq][lane][3] + cq1 + ckv.y + b2v2 + mm1.y * (-1e9f);

        float m0 = fmaxf(s00, s01);
        float m1 = fmaxf(s10, s11);
        #pragma unroll
        for (int o = 16; o > 0; o >>= 1) {
            m0 = fmaxf(m0, __shfl_xor_sync(0xffffffffu, m0, o));
            m1 = fmaxf(m1, __shfl_xor_sync(0xffffffffu, m1, o));
        }
        if (lane == 0) { red_m[0][jq] = m0; red_m[1][jq] = m1; }
    }
    __syncthreads();

    if (jh == 0) {
        float g0 = red_m[0][0], g1 = red_m[1][0];
        #pragma unroll
        for (int w = 1; w < 8; w++) { g0 = fmaxf(g0, red_m[0][w]); g1 = fmaxf(g1, red_m[1][w]); }

        s00 = __expf(s00 - g0);
        s01 = __expf(s01 - g0);
        s10 = __expf(s10 - g1);
        s11 = __expf(s11 - g1);
        float sum0 = s00 + s01;
        float sum1 = s10 + s11;
        #pragma unroll
        for (int o = 16; o > 0; o >>= 1) {
            sum0 += __shfl_xor_sync(0xffffffffu, sum0, o);
            sum1 += __shfl_xor_sync(0xffffffffu, sum1, o);
        }
        if (lane == 0) { red_s[0][jq] = sum0; red_s[1][jq] = sum1; }
    }
    __syncthreads();

    if (jh == 0) {
        float t0 = 0.f, t1 = 0.f;
        #pragma unroll
        for (int w = 0; w < 8; w++) { t0 += red_s[0][w]; t1 += red_s[1][w]; }
        float inv0 = 1.f / t0, inv1 = 1.f / t1;

        int jp = jq * 32 + lane;
        float2 a0 = make_float2(s00 * inv0, s01 * inv0);
        float2 a1 = make_float2(s10 * inv1, s11 * inv1);
        ((float2*)attn_s[0])[jp] = a0;
        ((float2*)attn_s[1])[jp] = a1;
        float2* aout = (float2*)(out + (size_t)NB * L * DD + (size_t)row0 * L);
        aout[jp]          = a0;
        aout[L / 2 + jp]  = a1;
    }
    __syncthreads();

    // ---- attn @ vp: each of 16 warps covers 32 j; vv reused for both rows
    float ox0 = 0.f, oy0 = 0.f, ox1 = 0.f, oy1 = 0.f;
    const float2* vp2 = (const float2*)(g_vp + (size_t)b * L * DD);
    #pragma unroll 4
    for (int jj = 0; jj < 32; jj++) {
        int j = warp * 32 + jj;
        float2 vv = __ldg(vp2 + j * 32 + lane);
        float a0 = attn_s[0][j];
        float a1 = attn_s[1][j];
        ox0 += a0 * vv.x; oy0 += a0 * vv.y;
        ox1 += a1 * vv.x; oy1 += a1 * vv.y;
    }
    o_part[0][warp][2 * lane]     = ox0;
    o_part[0][warp][2 * lane + 1] = oy0;
    o_part[1][warp][2 * lane]     = ox1;
    o_part[1][warp][2 * lane + 1] = oy1;
    __syncthreads();

    // ---- warps 0,1 reduce partials + output projection (warp w -> row w)
    if (warp < 2) {
        int r  = warp;
        int d0 = 2 * lane;
        float fox = 0.f, foy = 0.f;
        #pragma unroll
        for (int w = 0; w < 16; w++) {
            fox += o_part[r][w][d0];
            foy += o_part[r][w][d0 + 1];
        }
        o_part[r][0][d0]     = fox;
        o_part[r][0][d0 + 1] = foy;
        __syncwarp();

        float f0 = db[d0], f1 = db[d0 + 1];
        const float2* Wd2 = (const float2*)Wd;
        #pragma unroll 8
        for (int e = 0; e < DD; e++) {
            float ov = o_part[r][0][e];
            float2 wv = __ldg(Wd2 + e * 32 + lane);
            f0 += ov * wv.x;
            f1 += ov * wv.y;
        }
        out[(row0 + r) * DD + d0]     = f0;
        out[(row0 + r) * DD + d0 + 1] = f1;
    }
}

// ---------------------------------------------------------------------------
// Inputs (metadata order): q, k, v, mask, Ww, wb, Wd, db, W1, b1, W2, b2
// Output: [out (B,H,LQ,D) | attn (B,H,LQ,LK)] as float32
// ---------------------------------------------------------------------------
extern "C" void kernel_launch(void* const* d_in, const int* in_sizes, int n_in,
                              void* d_out, int out_size)
{
    const float* q    = (const float*)d_in[0];
    const float* k    = (const float*)d_in[1];
    const float* v    = (const float*)d_in[2];
    const float* mask = (const float*)d_in[3];
    const float* Ww   = (const float*)d_in[4];
    const float* wb   = (const float*)d_in[5];
    const float* Wd   = (const float*)d_in[6];
    const float* db   = (const float*)d_in[7];
    const float* W1   = (const float*)d_in[8];
    const float* b1   = (const float*)d_in[9];
    const float* W2   = (const float*)d_in[10];
    const float* b2   = (const float*)d_in[11];
    float* out = (float*)d_out;

    prep_kernel<<<NB * (L / 4), 256>>>(q, k, v, Ww, wb, W1, b1, W2);
    attn_kernel<<<NB * (L / 2), 512>>>(mask, Wd, db, W2, b2, out);
}

// round 13
// speedup vs baseline: 1.3614x; 1.3614x over previous
#include <cuda_runtime.h>
#include <cuda_bf16.h>

// Problem constants: B=2, H=1, LQ=LK=512, D=64, HID=128
#define NB   2
#define L    512
#define DD   64
#define HID  128

// Scratch (allocation-free rule: __device__ globals)
__device__ float  g_vp[NB * L * DD];             // projected V
__device__ float  g_qaqb[NB * L * HID * 2];      // interleaved (qa, qb) per (row, h)
__device__ float2 g_kbkaT[NB * HID * L];         // TRANSPOSED: [b][h][j] -> (kb+b1, ka+b1)
__device__ float  g_Cq[NB * L];                  // Σ_h (qa+qb)·w2/2 per q-row
__device__ float  g_Ck[NB * L];                  // Σ_h (kb'+ka')·w2/2 per k-row

// ---------------------------------------------------------------------------
// Kernel A: projections + pairwise-MLP feature precompute + rank-1 terms.
// grid = NB * (L/4) = 256 blocks, 256 threads.
// ---------------------------------------------------------------------------
__global__ __launch_bounds__(256) void prep_kernel(
    const float* __restrict__ q, const float* __restrict__ k,
    const float* __restrict__ v, const float* __restrict__ Ww,
    const float* __restrict__ wb, const float* __restrict__ W1,
    const float* __restrict__ b1, const float* __restrict__ W2)
{
    __shared__ float q_s[4][DD], k_s[4][DD], v_s[4][DD];
    __shared__ float qp_s[4][DD], kp_s[4][DD];
    __shared__ float red_c[8][4];        // per-warp partial rank-1 sums

    const int tid  = threadIdx.x;
    const int b    = blockIdx.x >> 7;
    const int r0   = (blockIdx.x & 127) * 4;
    const int base = (b * L + r0) * DD;

    {
        int r = tid >> 6, e = tid & 63;
        q_s[r][e] = q[base + tid];
        k_s[r][e] = k[base + tid];
        v_s[r][e] = v[base + tid];
    }
    __syncthreads();

    {
        int pj = tid >> 6, d = tid & 63;
        if (pj < 3) {
            const float (*src)[DD] = (pj == 0) ? q_s : (pj == 1) ? k_s : v_s;
            float acc[4];
            float bias = wb[d];
            #pragma unroll
            for (int r = 0; r < 4; r++) acc[r] = bias;
            #pragma unroll 8
            for (int e = 0; e < DD; e++) {
                float w = Ww[e * DD + d];
                #pragma unroll
                for (int r = 0; r < 4; r++) acc[r] += src[r][e] * w;
            }
            #pragma unroll
            for (int r = 0; r < 4; r++) {
                if (pj == 0)      qp_s[r][d] = acc[r];
                else if (pj == 1) kp_s[r][d] = acc[r];
                else              g_vp[base + r * DD + d] = acc[r];
            }
        }
    }
    __syncthreads();

    {
        int half = tid >> 7;     // 0: q-features, 1: k-features
        int h    = tid & 127;
        const float (*src)[DD] = half ? kp_s : qp_s;
        float accA[4] = {0.f, 0.f, 0.f, 0.f};   // · W1q
        float accB[4] = {0.f, 0.f, 0.f, 0.f};   // · W1k
        #pragma unroll 8
        for (int e = 0; e < DD; e++) {
            float w1q = W1[e * HID + h];
            float w1k = W1[(DD + e) * HID + h];
            #pragma unroll
            for (int r = 0; r < 4; r++) {
                float x = src[r][e];
                accA[r] += x * w1q;
                accB[r] += x * w1k;
            }
        }
        float bb = b1[h];
        float w2h = 0.5f * W2[h];
        float c[4];
        #pragma unroll
        for (int r = 0; r < 4; r++) {
            if (!half) {
                int off = ((b * L + r0 + r) * HID + h) * 2;
                g_qaqb[off + 0] = accA[r];                 // qa
                g_qaqb[off + 1] = accB[r];                 // qb
                c[r] = (accA[r] + accB[r]) * w2h;          // (qa+qb)·w2/2
            } else {
                float kb = accB[r] + bb, ka = accA[r] + bb;
                g_kbkaT[(b * HID + h) * L + (r0 + r)] = make_float2(kb, ka);
                c[r] = (kb + ka) * w2h;                    // (kb'+ka')·w2/2
            }
        }
        // block-reduce c over the 128 h of each half (4 warps per half)
        #pragma unroll
        for (int r = 0; r < 4; r++) {
            #pragma unroll
            for (int o = 16; o > 0; o >>= 1)
                c[r] += __shfl_xor_sync(0xffffffffu, c[r], o);
        }
        int warp = tid >> 5;
        if ((tid & 31) == 0) {
            #pragma unroll
            for (int r = 0; r < 4; r++) red_c[warp][r] = c[r];
        }
    }
    __syncthreads();

    if (tid < 8) {
        int half = tid >> 2, r = tid & 3;
        int w0 = half * 4;
        float s = red_c[w0][r] + red_c[w0 + 1][r] + red_c[w0 + 2][r] + red_c[w0 + 3][r];
        if (half == 0) g_Cq[b * L + r0 + r] = s;
        else           g_Ck[b * L + r0 + r] = s;
    }
}

// ---------------------------------------------------------------------------
// Kernel B: grid = NB*(L/4) = 256 blocks, 512 threads = 16 warps, 2 blocks/SM.
// Block covers 4 i-rows (all 256 blocks resident in one wave).
// Warp (jh, jq): jh = h-half (64 h), jq = j-slice of 64 j; lane owns a j-pair.
// One LDG.128 of kk feeds 32 fma-ops (4 rows x 2 j x 2 branches x 2 ops).
// relu(x) = (x+|x|)/2 — rank-1 parts from prep, pairwise is FADD+FFMA(|t|).
// ---------------------------------------------------------------------------
__global__ __launch_bounds__(512, 2) void attn_kernel(
    const float* __restrict__ mask, const float* __restrict__ Wd,
    const float* __restrict__ db,   const float* __restrict__ W2,
    const float* __restrict__ b2,   float* __restrict__ out)
{
    __shared__ float4 qq_s[HID][2];      // per h: (qa,qb) rows 0,1 | rows 2,3
    __shared__ float  w2_s[HID];         // w2/2
    __shared__ float  attn_s[4][L];
    __shared__ float  sp[8][32][8];      // jh=1 partials [jq][lane][row*2+jp]
    __shared__ float  red_m[4][8], red_s[4][8];
    __shared__ float  o_part[4][16][DD];

    const int tid   = threadIdx.x;
    const int warp  = tid >> 5;
    const int lane  = tid & 31;
    const int jq    = warp & 7;          // j-slice
    const int jh    = warp >> 3;         // h-half
    const int b     = blockIdx.x >> 7;   // / 128
    const int itile = blockIdx.x & 127;
    const int row0  = b * L + itile * 4;

    // Stage q-features (4 rows) + W2/2
    if (tid < 256) {
        int h = tid >> 1, p = tid & 1;   // p: row-pair (0: rows 0-1, 1: rows 2-3)
        const float2* q2 = (const float2*)g_qaqb;
        float2 a0 = q2[(size_t)(row0 + 2 * p)     * HID + h];
        float2 a1 = q2[(size_t)(row0 + 2 * p + 1) * HID + h];
        qq_s[h][p] = make_float4(a0.x, a0.y, a1.x, a1.y);
    } else if (tid < 256 + HID) {
        w2_s[tid - 256] = 0.5f * W2[tid - 256];
    }
    __syncthreads();

    // ---- |.|-part of scores over own h-half
    const float4* kt = reinterpret_cast<const float4*>(
        g_kbkaT + (size_t)(b * HID + jh * 64) * L) + jq * 32 + lane;

    float acc[4][2];
    #pragma unroll
    for (int r = 0; r < 4; r++) { acc[r][0] = 0.f; acc[r][1] = 0.f; }

    #pragma unroll 2
    for (int hh = 0; hh < 64; hh++) {
        float4 kk  = __ldg(kt + hh * (L / 2));    // (kb_j0, ka_j0, kb_j1, ka_j1)
        float4 q01 = qq_s[jh * 64 + hh][0];       // (qa0,qb0,qa1,qb1)
        float4 q23 = qq_s[jh * 64 + hh][1];       // (qa2,qb2,qa3,qb3)
        float  wh  = w2_s[jh * 64 + hh];
        acc[0][0] = fmaf(fabsf(q01.x + kk.x), wh, acc[0][0]);
        acc[0][0] = fmaf(fabsf(q01.y + kk.y), wh, acc[0][0]);
        acc[0][1] = fmaf(fabsf(q01.x + kk.z), wh, acc[0][1]);
        acc[0][1] = fmaf(fabsf(q01.y + kk.w), wh, acc[0][1]);
        acc[1][0] = fmaf(fabsf(q01.z + kk.x), wh, acc[1][0]);
        acc[1][0] = fmaf(fabsf(q01.w + kk.y), wh, acc[1][0]);
        acc[1][1] = fmaf(fabsf(q01.z + kk.z), wh, acc[1][1]);
        acc[1][1] = fmaf(fabsf(q01.w + kk.w), wh, acc[1][1]);
        acc[2][0] = fmaf(fabsf(q23.x + kk.x), wh, acc[2][0]);
        acc[2][0] = fmaf(fabsf(q23.y + kk.y), wh, acc[2][0]);
        acc[2][1] = fmaf(fabsf(q23.x + kk.z), wh, acc[2][1]);
        acc[2][1] = fmaf(fabsf(q23.y + kk.w), wh, acc[2][1]);
        acc[3][0] = fmaf(fabsf(q23.z + kk.x), wh, acc[3][0]);
        acc[3][0] = fmaf(fabsf(q23.w + kk.y), wh, acc[3][0]);
        acc[3][1] = fmaf(fabsf(q23.z + kk.z), wh, acc[3][1]);
        acc[3][1] = fmaf(fabsf(q23.w + kk.w), wh, acc[3][1]);
    }

    // combine h-halves: jh=1 dumps partials, jh=0 accumulates
    if (jh == 1) {
        #pragma unroll
        for (int r = 0; r < 4; r++) {
            sp[jq][lane][r * 2 + 0] = acc[r][0];
            sp[jq][lane][r * 2 + 1] = acc[r][1];
        }
    }
    __syncthreads();

    float s[4][2];
    if (jh == 0) {
        const float b2v2 = 2.f * b2[0];
        int jp = jq * 32 + lane;
        float2 ckv = ((const float2*)(g_Ck + (size_t)b * L))[jp];   // (Ck_j0, Ck_j1)
        #pragma unroll
        for (int r = 0; r < 4; r++) {
            float cq = g_Cq[row0 + r];
            float2 mm = __ldg((const float2*)(mask + (size_t)(row0 + r) * L) + jp);
            s[r][0] = acc[r][0] + sp[jq][lane][r * 2 + 0] + cq + ckv.x + b2v2 + mm.x * (-1e9f);
            s[r][1] = acc[r][1] + sp[jq][lane][r * 2 + 1] + cq + ckv.y + b2v2 + mm.y * (-1e9f);
        }

        float m[4];
        #pragma unroll
        for (int r = 0; r < 4; r++) {
            m[r] = fmaxf(s[r][0], s[r][1]);
            #pragma unroll
            for (int o = 16; o > 0; o >>= 1)
                m[r] = fmaxf(m[r], __shfl_xor_sync(0xffffffffu, m[r], o));
        }
        if (lane == 0) {
            #pragma unroll
            for (int r = 0; r < 4; r++) red_m[r][jq] = m[r];
        }
    }
    __syncthreads();

    if (jh == 0) {
        float sum[4];
        #pragma unroll
        for (int r = 0; r < 4; r++) {
            float g = red_m[r][0];
            #pragma unroll
            for (int w = 1; w < 8; w++) g = fmaxf(g, red_m[r][w]);
            s[r][0] = __expf(s[r][0] - g);
            s[r][1] = __expf(s[r][1] - g);
            sum[r]  = s[r][0] + s[r][1];
            #pragma unroll
            for (int o = 16; o > 0; o >>= 1)
                sum[r] += __shfl_xor_sync(0xffffffffu, sum[r], o);
        }
        if (lane == 0) {
            #pragma unroll
            for (int r = 0; r < 4; r++) red_s[r][jq] = sum[r];
        }
    }
    __syncthreads();

    if (jh == 0) {
        int jp = jq * 32 + lane;
        float2* aout = (float2*)(out + (size_t)NB * L * DD + (size_t)row0 * L);
        #pragma unroll
        for (int r = 0; r < 4; r++) {
            float t = 0.f;
            #pragma unroll
            for (int w = 0; w < 8; w++) t += red_s[r][w];
            float inv = 1.f / t;
            float2 a = make_float2(s[r][0] * inv, s[r][1] * inv);
            ((float2*)attn_s[r])[jp] = a;
            aout[(size_t)r * (L / 2) + jp] = a;
        }
    }
    __syncthreads();

    // ---- attn @ vp: each of 16 warps covers 32 j; vv reused for 4 rows
    float ox[4], oy[4];
    #pragma unroll
    for (int r = 0; r < 4; r++) { ox[r] = 0.f; oy[r] = 0.f; }
    const float2* vp2 = (const float2*)(g_vp + (size_t)b * L * DD);
    #pragma unroll 2
    for (int jj = 0; jj < 32; jj++) {
        int j = warp * 32 + jj;
        float2 vv = __ldg(vp2 + j * 32 + lane);
        #pragma unroll
        for (int r = 0; r < 4; r++) {
            float a = attn_s[r][j];
            ox[r] += a * vv.x;
            oy[r] += a * vv.y;
        }
    }
    #pragma unroll
    for (int r = 0; r < 4; r++) {
        o_part[r][warp][2 * lane]     = ox[r];
        o_part[r][warp][2 * lane + 1] = oy[r];
    }
    __syncthreads();

    // ---- warps 0-3 reduce partials + output projection (warp w -> row w)
    if (warp < 4) {
        int r  = warp;
        int d0 = 2 * lane;
        float fox = 0.f, foy = 0.f;
        #pragma unroll
        for (int w = 0; w < 16; w++) {
            fox += o_part[r][w][d0];
            foy += o_part[r][w][d0 + 1];
        }
        o_part[r][0][d0]     = fox;
        o_part[r][0][d0 + 1] = foy;
        __syncwarp();

        float f0 = db[d0], f1 = db[d0 + 1];
        const float2* Wd2 = (const float2*)Wd;
        #pragma unroll 8
        for (int e = 0; e < DD; e++) {
            float ov = o_part[r][0][e];
            float2 wv = __ldg(Wd2 + e * 32 + lane);
            f0 += ov * wv.x;
            f1 += ov * wv.y;
        }
        out[(row0 + r) * DD + d0]     = f0;
        out[(row0 + r) * DD + d0 + 1] = f1;
    }
}

// ---------------------------------------------------------------------------
// Inputs (metadata order): q, k, v, mask, Ww, wb, Wd, db, W1, b1, W2, b2
// Output: [out (B,H,LQ,D) | attn (B,H,LQ,LK)] as float32
// ---------------------------------------------------------------------------
extern "C" void kernel_launch(void* const* d_in, const int* in_sizes, int n_in,
                              void* d_out, int out_size)
{
    const float* q    = (const float*)d_in[0];
    const float* k    = (const float*)d_in[1];
    const float* v    = (const float*)d_in[2];
    const float* mask = (const float*)d_in[3];
    const float* Ww   = (const float*)d_in[4];
    const float* wb   = (const float*)d_in[5];
    const float* Wd   = (const float*)d_in[6];
    const float* db   = (const float*)d_in[7];
    const float* W1   = (const float*)d_in[8];
    const float* b1   = (const float*)d_in[9];
    const float* W2   = (const float*)d_in[10];
    const float* b2   = (const float*)d_in[11];
    float* out = (float*)d_out;

    prep_kernel<<<NB * (L / 4), 256>>>(q, k, v, Ww, wb, W1, b1, W2);
    attn_kernel<<<NB * (L / 4), 512>>>(mask, Wd, db, W2, b2, out);
}